// round 1
// baseline (speedup 1.0000x reference)
#include <cuda_runtime.h>

#define NBINS 20
#define NACC  (3 * NBINS)

// Global double-precision accumulators: A[0..19], B[20..39], C[40..59]
// A_j = sum base*r^j ; B_j = sum base*r^j*p ; C_j = sum base*r^j*t
__device__ double g_acc[NACC];

__global__ void zero_acc_kernel() {
    int i = threadIdx.x;
    if (i < NACC) g_acc[i] = 0.0;
}

// ---- packed f32x2 helpers (Blackwell FFMA2 path, PTX-only) ----
__device__ __forceinline__ unsigned long long pk2(float lo, float hi) {
    unsigned long long r;
    asm("mov.b64 %0, {%1, %2};" : "=l"(r)
        : "r"(__float_as_uint(lo)), "r"(__float_as_uint(hi)));
    return r;
}
__device__ __forceinline__ void upk2(unsigned long long v, float& lo, float& hi) {
    unsigned int a, b;
    asm("mov.b64 {%0, %1}, %2;" : "=r"(a), "=r"(b) : "l"(v));
    lo = __uint_as_float(a);
    hi = __uint_as_float(b);
}
__device__ __forceinline__ unsigned long long fma2(unsigned long long a,
                                                   unsigned long long b,
                                                   unsigned long long c) {
    unsigned long long d;
    asm("fma.rn.f32x2 %0, %1, %2, %3;" : "=l"(d) : "l"(a), "l"(b), "l"(c));
    return d;
}
__device__ __forceinline__ unsigned long long add2(unsigned long long a,
                                                   unsigned long long b) {
    unsigned long long d;
    asm("add.rn.f32x2 %0, %1, %2;" : "=l"(d) : "l"(a), "l"(b));
    return d;
}
__device__ __forceinline__ unsigned long long mul2(unsigned long long a,
                                                   unsigned long long b) {
    unsigned long long d;
    asm("mul.rn.f32x2 %0, %1, %2;" : "=l"(d) : "l"(a), "l"(b));
    return d;
}

// r = exp(2*delta*p/T) with delta = 1/19, T = 0.1  ->  exp(p * 20/19)
#define KR (20.0f / 19.0f)
#define KB (-10.0f)   // base = exp(-p*p/T) = exp(-10*p*p)

__global__ void __launch_bounds__(128, 3)
ace_main_kernel(const float* __restrict__ preds,
                const float* __restrict__ targs,
                int n) {
    unsigned long long A[NBINS], B[NBINS], C[NBINS];
#pragma unroll
    for (int j = 0; j < NBINS; j++) { A[j] = 0ull; B[j] = 0ull; C[j] = 0ull; }

    const int n4 = n >> 2;
    const float4* p4 = (const float4*)preds;
    const float4* t4 = (const float4*)targs;
    const int stride = gridDim.x * blockDim.x;

    for (int g = blockIdx.x * blockDim.x + threadIdx.x; g < n4; g += stride) {
        float4 pv = p4[g];
        float4 tv = t4[g];

#pragma unroll
        for (int half = 0; half < 2; half++) {
            float p0 = half ? pv.z : pv.x;
            float p1 = half ? pv.w : pv.y;
            float t0 = half ? tv.z : tv.x;
            float t1 = half ? tv.w : tv.y;

            float b0 = __expf(KB * p0 * p0);
            float b1 = __expf(KB * p1 * p1);
            float r0 = __expf(KR * p0);
            float r1 = __expf(KR * p1);

            unsigned long long s  = pk2(b0, b1);
            unsigned long long rr = pk2(r0, r1);
            unsigned long long pp = pk2(p0, p1);
            unsigned long long tt = pk2(t0, t1);

#pragma unroll
            for (int j = 0; j < NBINS; j++) {
                A[j] = add2(A[j], s);
                B[j] = fma2(s, pp, B[j]);
                C[j] = fma2(s, tt, C[j]);
                if (j < NBINS - 1) s = mul2(s, rr);
            }
        }
    }

    // ---- scalar tail (n not divisible by 4; normally empty) ----
    {
        int base4 = n4 << 2;
        int rem = n - base4;
        if (blockIdx.x == 0 && threadIdx.x < rem) {
            float p0 = preds[base4 + threadIdx.x];
            float t0 = targs[base4 + threadIdx.x];
            float s = __expf(KB * p0 * p0);
            float r = __expf(KR * p0);
            for (int j = 0; j < NBINS; j++) {
                atomicAdd(&g_acc[j],      (double)s);
                atomicAdd(&g_acc[20 + j], (double)(s * p0));
                atomicAdd(&g_acc[40 + j], (double)(s * t0));
                s *= r;
            }
        }
    }

    // ---- block reduction: shuffle within warp, shared across warps ----
    __shared__ float sh[4][NACC];
    int lane = threadIdx.x & 31;
    int warp = threadIdx.x >> 5;

#pragma unroll
    for (int k = 0; k < NACC; k++) {
        unsigned long long v = (k < NBINS) ? A[k]
                             : (k < 2 * NBINS) ? B[k - NBINS]
                             : C[k - 2 * NBINS];
        float lo, hi;
        upk2(v, lo, hi);
        float s = lo + hi;
#pragma unroll
        for (int off = 16; off; off >>= 1)
            s += __shfl_down_sync(0xffffffffu, s, off);
        if (lane == 0) sh[warp][k] = s;
    }
    __syncthreads();

    if (threadIdx.x < NACC) {
        double v = (double)sh[0][threadIdx.x] + (double)sh[1][threadIdx.x] +
                   (double)sh[2][threadIdx.x] + (double)sh[3][threadIdx.x];
        atomicAdd(&g_acc[threadIdx.x], v);
    }
}

__global__ void finalize_kernel(float* out, int out_size) {
    if (blockIdx.x == 0 && threadIdx.x == 0) {
        double loss = 0.0;
        for (int j = 0; j < NBINS; j++) {
            double c = (double)j / (double)(NBINS - 1);
            double k = exp(-c * c / 0.1);      // restores the cancelled k_j
            double ws = k * g_acc[j];
            if (ws != 0.0) {
                double e = (k * g_acc[20 + j]) / (ws + 1e-8);
                double o = (k * g_acc[40 + j]) / (ws + 1e-8);
                loss += fabs(e - o);
            }
        }
        float res = (float)(loss / NBINS);
        for (int i = 0; i < out_size; i++) out[i] = res;
    }
}

extern "C" void kernel_launch(void* const* d_in, const int* in_sizes, int n_in,
                              void* d_out, int out_size) {
    const float* preds = (const float*)d_in[0];
    const float* targs = (const float*)d_in[1];
    int n = in_sizes[0];

    zero_acc_kernel<<<1, 64>>>();
    ace_main_kernel<<<444, 128>>>(preds, targs, n);   // 148 SMs x 3 CTAs: one wave
    finalize_kernel<<<1, 32>>>((float*)d_out, out_size);
}

// round 2
// speedup vs baseline: 1.2020x; 1.2020x over previous
#include <cuda_runtime.h>

#define NBINS 20
#define NACC  (2 * NBINS)   // A[0..19] = sum w ; D[20..39] = sum w*(p-t)

__device__ double g_acc[NACC];
__device__ unsigned int g_count;

// ---- packed f32x2 helpers (Blackwell FFMA2 path, PTX-only) ----
__device__ __forceinline__ unsigned long long pk2(float lo, float hi) {
    unsigned long long r;
    asm("mov.b64 %0, {%1, %2};" : "=l"(r)
        : "r"(__float_as_uint(lo)), "r"(__float_as_uint(hi)));
    return r;
}
__device__ __forceinline__ void upk2(unsigned long long v, float& lo, float& hi) {
    unsigned int a, b;
    asm("mov.b64 {%0, %1}, %2;" : "=r"(a), "=r"(b) : "l"(v));
    lo = __uint_as_float(a);
    hi = __uint_as_float(b);
}
__device__ __forceinline__ unsigned long long fma2(unsigned long long a,
                                                   unsigned long long b,
                                                   unsigned long long c) {
    unsigned long long d;
    asm("fma.rn.f32x2 %0, %1, %2, %3;" : "=l"(d) : "l"(a), "l"(b), "l"(c));
    return d;
}
__device__ __forceinline__ unsigned long long add2(unsigned long long a,
                                                   unsigned long long b) {
    unsigned long long d;
    asm("add.rn.f32x2 %0, %1, %2;" : "=l"(d) : "l"(a), "l"(b));
    return d;
}
__device__ __forceinline__ unsigned long long mul2(unsigned long long a,
                                                   unsigned long long b) {
    unsigned long long d;
    asm("mul.rn.f32x2 %0, %1, %2;" : "=l"(d) : "l"(a), "l"(b));
    return d;
}

// r = exp(2*delta*p/T), delta = 1/19, T = 0.1  ->  exp(p * 20/19)
#define KR (20.0f / 19.0f)
#define KB (-10.0f)   // base = exp(-p*p/T) = exp(-10*p*p)

__global__ void __launch_bounds__(128, 4)
ace_fused_kernel(const float* __restrict__ preds,
                 const float* __restrict__ targs,
                 int n, float* __restrict__ out, int out_size) {
    unsigned long long A[NBINS], D[NBINS];
#pragma unroll
    for (int j = 0; j < NBINS; j++) { A[j] = 0ull; D[j] = 0ull; }

    const unsigned long long NEG1 = pk2(-1.0f, -1.0f);

    const int n4 = n >> 2;
    const float4* p4 = (const float4*)preds;
    const float4* t4 = (const float4*)targs;
    const int stride = gridDim.x * blockDim.x;

    for (int g = blockIdx.x * blockDim.x + threadIdx.x; g < n4; g += stride) {
        float4 pv = p4[g];
        float4 tv = t4[g];

#pragma unroll
        for (int half = 0; half < 2; half++) {
            float p0 = half ? pv.z : pv.x;
            float p1 = half ? pv.w : pv.y;
            float t0 = half ? tv.z : tv.x;
            float t1 = half ? tv.w : tv.y;

            float b0 = __expf(KB * p0 * p0);
            float b1 = __expf(KB * p1 * p1);
            float r0 = __expf(KR * p0);
            float r1 = __expf(KR * p1);

            unsigned long long s  = pk2(b0, b1);
            unsigned long long rr = pk2(r0, r1);
            unsigned long long pp = pk2(p0, p1);
            unsigned long long tt = pk2(t0, t1);
            unsigned long long dd = fma2(tt, NEG1, pp);   // p - t

#pragma unroll
            for (int j = 0; j < NBINS; j++) {
                A[j] = add2(A[j], s);
                D[j] = fma2(s, dd, D[j]);
                if (j < NBINS - 1) s = mul2(s, rr);
            }
        }
    }

    // ---- scalar tail (n % 4; empty for this shape) ----
    {
        int base4 = n4 << 2;
        int rem = n - base4;
        if (blockIdx.x == 0 && threadIdx.x < rem) {
            float p0 = preds[base4 + threadIdx.x];
            float t0 = targs[base4 + threadIdx.x];
            float s = __expf(KB * p0 * p0);
            float r = __expf(KR * p0);
            float d = p0 - t0;
            for (int j = 0; j < NBINS; j++) {
                atomicAdd(&g_acc[j],         (double)s);
                atomicAdd(&g_acc[NBINS + j], (double)(s * d));
                s *= r;
            }
        }
    }

    // ---- block reduction: warp shuffles, then shared across warps ----
    __shared__ float sh[4][NACC];
    int lane = threadIdx.x & 31;
    int warp = threadIdx.x >> 5;

#pragma unroll
    for (int k = 0; k < NACC; k++) {
        unsigned long long v = (k < NBINS) ? A[k] : D[k - NBINS];
        float lo, hi;
        upk2(v, lo, hi);
        float s = lo + hi;
#pragma unroll
        for (int off = 16; off; off >>= 1)
            s += __shfl_down_sync(0xffffffffu, s, off);
        if (lane == 0) sh[warp][k] = s;
    }
    __syncthreads();

    if (threadIdx.x < NACC) {
        double v = (double)sh[0][threadIdx.x] + (double)sh[1][threadIdx.x] +
                   (double)sh[2][threadIdx.x] + (double)sh[3][threadIdx.x];
        atomicAdd(&g_acc[threadIdx.x], v);
    }
    __syncthreads();

    // ---- last block finalizes, writes out, and resets state ----
    __shared__ unsigned int s_is_last;
    if (threadIdx.x == 0) {
        __threadfence();
        unsigned int old = atomicAdd(&g_count, 1u);
        s_is_last = (old == gridDim.x - 1) ? 1u : 0u;
    }
    __syncthreads();

    if (s_is_last && threadIdx.x == 0) {
        __threadfence();
        double loss = 0.0;
        for (int j = 0; j < NBINS; j++) {
            double c = (double)j / (double)(NBINS - 1);
            double kj = exp(-c * c / 0.1);         // restores cancelled k_j
            double ws = kj * atomicAdd(&g_acc[j], 0.0);           // coherent read
            double nm = kj * atomicAdd(&g_acc[NBINS + j], 0.0);
            if (ws != 0.0) loss += fabs(nm) / (ws + 1e-8);
        }
        float res = (float)(loss / NBINS);
        for (int i = 0; i < out_size; i++) out[i] = res;
        // reset for next (graph-replayed) call
        for (int k = 0; k < NACC; k++) g_acc[k] = 0.0;
        g_count = 0u;
        __threadfence();
    }
}

extern "C" void kernel_launch(void* const* d_in, const int* in_sizes, int n_in,
                              void* d_out, int out_size) {
    const float* preds = (const float*)d_in[0];
    const float* targs = (const float*)d_in[1];
    int n = in_sizes[0];
    // 148 SMs x 4 CTAs/SM = one full wave at occupancy 4
    ace_fused_kernel<<<592, 128>>>(preds, targs, n, (float*)d_out, out_size);
}

// round 3
// speedup vs baseline: 1.2099x; 1.0065x over previous
#include <cuda_runtime.h>

#define NBINS 20
#define NHALF 10
#define NACC  (2 * NBINS)   // g_acc[0..19] = sum w ; g_acc[20..39] = sum w*(p-t)

__device__ double g_acc[NACC];
__device__ unsigned int g_count;

// ---- packed f32x2 helpers (Blackwell FFMA2 path, PTX-only) ----
__device__ __forceinline__ unsigned long long pk2(float lo, float hi) {
    unsigned long long r;
    asm("mov.b64 %0, {%1, %2};" : "=l"(r)
        : "r"(__float_as_uint(lo)), "r"(__float_as_uint(hi)));
    return r;
}
__device__ __forceinline__ void upk2(unsigned long long v, float& lo, float& hi) {
    unsigned int a, b;
    asm("mov.b64 {%0, %1}, %2;" : "=r"(a), "=r"(b) : "l"(v));
    lo = __uint_as_float(a);
    hi = __uint_as_float(b);
}
__device__ __forceinline__ unsigned long long fma2(unsigned long long a,
                                                   unsigned long long b,
                                                   unsigned long long c) {
    unsigned long long d;
    asm("fma.rn.f32x2 %0, %1, %2, %3;" : "=l"(d) : "l"(a), "l"(b), "l"(c));
    return d;
}
__device__ __forceinline__ unsigned long long add2(unsigned long long a,
                                                   unsigned long long b) {
    unsigned long long d;
    asm("add.rn.f32x2 %0, %1, %2;" : "=l"(d) : "l"(a), "l"(b));
    return d;
}
__device__ __forceinline__ unsigned long long mul2(unsigned long long a,
                                                   unsigned long long b) {
    unsigned long long d;
    asm("mul.rn.f32x2 %0, %1, %2;" : "=l"(d) : "l"(a), "l"(b));
    return d;
}

// r = exp(2*delta*p/T), delta = 1/19, T = 0.1  ->  exp(p * 20/19)
#define KR (20.0f / 19.0f)
#define KB (-10.0f)   // base = exp(-p*p/T) = exp(-10*p*p)

__global__ void __launch_bounds__(128, 4)
ace_fused_kernel(const float* __restrict__ preds,
                 const float* __restrict__ targs,
                 int n, float* __restrict__ out, int out_size) {
    // Packed accumulators: lane0 = bin j, lane1 = bin j+10.
    unsigned long long A2[NHALF], D2[NHALF];
#pragma unroll
    for (int j = 0; j < NHALF; j++) { A2[j] = 0ull; D2[j] = 0ull; }

    const int n4 = n >> 2;
    const float4* p4 = (const float4*)preds;
    const float4* t4 = (const float4*)targs;
    const int stride = gridDim.x * blockDim.x;

    int g = blockIdx.x * blockDim.x + threadIdx.x;
    if (g < n4) {
        float4 pv = p4[g];
        float4 tv = t4[g];
        while (1) {
            int gn = g + stride;
            float4 pv_n, tv_n;
            bool more = (gn < n4);
            if (more) { pv_n = p4[gn]; tv_n = t4[gn]; }   // prefetch

            const float pe[4] = {pv.x, pv.y, pv.z, pv.w};
            const float te[4] = {tv.x, tv.y, tv.z, tv.w};

            unsigned long long s2[4], rr2[4], dd2[4];
#pragma unroll
            for (int e = 0; e < 4; e++) {
                float p = pe[e];
                float t = te[e];
                float bs = __expf(KB * p * p);     // exp(-10 p^2)
                float r  = __expf(KR * p);         // exp(20p/19)
                float r2  = r * r;
                float r4  = r2 * r2;
                float r8  = r4 * r4;
                float r10 = r8 * r2;
                float d = p - t;
                s2[e]  = pk2(bs, bs * r10);        // lanes: bin0 / bin10 seeds
                rr2[e] = pk2(r, r);
                dd2[e] = pk2(d, d);
            }

#pragma unroll
            for (int j = 0; j < NHALF; j++) {
#pragma unroll
                for (int e = 0; e < 4; e++) {
                    A2[j] = add2(A2[j], s2[e]);
                    D2[j] = fma2(s2[e], dd2[e], D2[j]);
                    if (j < NHALF - 1) s2[e] = mul2(s2[e], rr2[e]);
                }
            }

            if (!more) break;
            pv = pv_n; tv = tv_n; g = gn;
        }
    }

    // ---- scalar tail (n % 4; empty for this shape) ----
    {
        int base4 = n4 << 2;
        int rem = n - base4;
        if (blockIdx.x == 0 && threadIdx.x < rem) {
            float p0 = preds[base4 + threadIdx.x];
            float t0 = targs[base4 + threadIdx.x];
            float s = __expf(KB * p0 * p0);
            float r = __expf(KR * p0);
            float d = p0 - t0;
            for (int j = 0; j < NBINS; j++) {
                atomicAdd(&g_acc[j],         (double)s);
                atomicAdd(&g_acc[NBINS + j], (double)(s * d));
                s *= r;
            }
        }
    }

    // ---- block reduction: warp shuffles, then shared across warps ----
    __shared__ float sh[4][NACC];
    int lane = threadIdx.x & 31;
    int warp = threadIdx.x >> 5;

#pragma unroll
    for (int j = 0; j < NHALF; j++) {
        float alo, ahi, dlo, dhi;
        upk2(A2[j], alo, ahi);
        upk2(D2[j], dlo, dhi);
        float v[4] = {alo, ahi, dlo, dhi};
        // bin indices: A: j, j+10 ; D: 20+j, 30+j
        int idx[4] = {j, j + NHALF, NBINS + j, NBINS + NHALF + j};
#pragma unroll
        for (int q = 0; q < 4; q++) {
            float s = v[q];
#pragma unroll
            for (int off = 16; off; off >>= 1)
                s += __shfl_down_sync(0xffffffffu, s, off);
            if (lane == 0) sh[warp][idx[q]] = s;
        }
    }
    __syncthreads();

    if (threadIdx.x < NACC) {
        double v = (double)sh[0][threadIdx.x] + (double)sh[1][threadIdx.x] +
                   (double)sh[2][threadIdx.x] + (double)sh[3][threadIdx.x];
        atomicAdd(&g_acc[threadIdx.x], v);
    }
    __syncthreads();

    // ---- last block finalizes, writes out, resets state ----
    __shared__ unsigned int s_is_last;
    if (threadIdx.x == 0) {
        __threadfence();
        unsigned int old = atomicAdd(&g_count, 1u);
        s_is_last = (old == gridDim.x - 1) ? 1u : 0u;
    }
    __syncthreads();

    if (s_is_last && threadIdx.x == 0) {
        __threadfence();
        double loss = 0.0;
        for (int j = 0; j < NBINS; j++) {
            double c = (double)j / (double)(NBINS - 1);
            double kj = exp(-c * c / 0.1);         // restores cancelled k_j
            double ws = kj * atomicAdd(&g_acc[j], 0.0);
            double nm = kj * atomicAdd(&g_acc[NBINS + j], 0.0);
            if (ws != 0.0) loss += fabs(nm) / (ws + 1e-8);
        }
        float res = (float)(loss / NBINS);
        for (int i = 0; i < out_size; i++) out[i] = res;
        for (int k = 0; k < NACC; k++) g_acc[k] = 0.0;
        g_count = 0u;
        __threadfence();
    }
}

extern "C" void kernel_launch(void* const* d_in, const int* in_sizes, int n_in,
                              void* d_out, int out_size) {
    const float* preds = (const float*)d_in[0];
    const float* targs = (const float*)d_in[1];
    int n = in_sizes[0];
    // 148 SMs x 4 CTAs/SM = one full wave at occupancy 4
    ace_fused_kernel<<<592, 128>>>(preds, targs, n, (float*)d_out, out_size);
}

// round 4
// speedup vs baseline: 1.3194x; 1.0905x over previous
#include <cuda_runtime.h>

#define NBINS 20
#define NHALF 10
#define NACC  (2 * NBINS)   // g_acc[0..19] = sum w ; g_acc[20..39] = sum w*(p-t)

__device__ double g_acc[NACC];
__device__ unsigned int g_count;

// ---- packed f32x2 helpers (Blackwell FFMA2 path, PTX-only) ----
__device__ __forceinline__ unsigned long long pk2(float lo, float hi) {
    unsigned long long r;
    asm("mov.b64 %0, {%1, %2};" : "=l"(r)
        : "r"(__float_as_uint(lo)), "r"(__float_as_uint(hi)));
    return r;
}
__device__ __forceinline__ void upk2(unsigned long long v, float& lo, float& hi) {
    unsigned int a, b;
    asm("mov.b64 {%0, %1}, %2;" : "=r"(a), "=r"(b) : "l"(v));
    lo = __uint_as_float(a);
    hi = __uint_as_float(b);
}
__device__ __forceinline__ unsigned long long fma2(unsigned long long a,
                                                   unsigned long long b,
                                                   unsigned long long c) {
    unsigned long long d;
    asm("fma.rn.f32x2 %0, %1, %2, %3;" : "=l"(d) : "l"(a), "l"(b), "l"(c));
    return d;
}
__device__ __forceinline__ unsigned long long add2(unsigned long long a,
                                                   unsigned long long b) {
    unsigned long long d;
    asm("add.rn.f32x2 %0, %1, %2;" : "=l"(d) : "l"(a), "l"(b));
    return d;
}
__device__ __forceinline__ unsigned long long mul2(unsigned long long a,
                                                   unsigned long long b) {
    unsigned long long d;
    asm("mul.rn.f32x2 %0, %1, %2;" : "=l"(d) : "l"(a), "l"(b));
    return d;
}

// delta = 1/19, T = 0.1:
//   r    = exp(2*delta*p/T)            = exp(p * 20/19)
//   base = exp(-p^2/T)                 = exp(-10 p^2)
//   lane1 seed = base * r^10           = exp(-10 p^2 + p * 200/19)   (direct MUFU)
#define KR   (20.0f / 19.0f)
#define KR10 (200.0f / 19.0f)

__global__ void __launch_bounds__(128, 6)
ace_fused_kernel(const float* __restrict__ preds,
                 const float* __restrict__ targs,
                 int n, float* __restrict__ out, int out_size) {
    // Packed accumulators: lane0 = bin j, lane1 = bin j+10.
    unsigned long long A2[NHALF], D2[NHALF];
#pragma unroll
    for (int j = 0; j < NHALF; j++) { A2[j] = 0ull; D2[j] = 0ull; }

    const int n4 = n >> 2;
    const float4* p4 = (const float4*)preds;
    const float4* t4 = (const float4*)targs;
    const int stride = gridDim.x * blockDim.x;

    int g = blockIdx.x * blockDim.x + threadIdx.x;
    if (g < n4) {
        float4 pv = p4[g];
        float4 tv = t4[g];
        while (1) {
            int gn = g + stride;
            float4 pv_n, tv_n;
            bool more = (gn < n4);
            if (more) { pv_n = p4[gn]; tv_n = t4[gn]; }   // prefetch 1 ahead

            // process the 4 loaded elements as two 2-element groups (bounded ILP state)
#pragma unroll
            for (int grp = 0; grp < 2; grp++) {
                float pa = grp ? pv.z : pv.x;
                float pb = grp ? pv.w : pv.y;
                float ta = grp ? tv.z : tv.x;
                float tb = grp ? tv.w : tv.y;

                float qa = pa * pa;
                float qb = pb * pb;
                float sa_lo = __expf(-10.0f * qa);
                float sb_lo = __expf(-10.0f * qb);
                float sa_hi = __expf(fmaf(KR10, pa, -10.0f * qa));
                float sb_hi = __expf(fmaf(KR10, pb, -10.0f * qb));
                float ra = __expf(KR * pa);
                float rb = __expf(KR * pb);
                float da = pa - ta;
                float db = pb - tb;

                unsigned long long sA = pk2(sa_lo, sa_hi);
                unsigned long long sB = pk2(sb_lo, sb_hi);
                unsigned long long rA = pk2(ra, ra);
                unsigned long long rB = pk2(rb, rb);
                unsigned long long dA = pk2(da, da);
                unsigned long long dB = pk2(db, db);

#pragma unroll
                for (int j = 0; j < NHALF; j++) {
                    A2[j] = add2(A2[j], sA);
                    D2[j] = fma2(sA, dA, D2[j]);
                    A2[j] = add2(A2[j], sB);
                    D2[j] = fma2(sB, dB, D2[j]);
                    if (j < NHALF - 1) {
                        sA = mul2(sA, rA);
                        sB = mul2(sB, rB);
                    }
                }
            }

            if (!more) break;
            pv = pv_n; tv = tv_n; g = gn;
        }
    }

    // ---- scalar tail (n % 4; empty for this shape) ----
    {
        int base4 = n4 << 2;
        int rem = n - base4;
        if (blockIdx.x == 0 && threadIdx.x < rem) {
            float p0 = preds[base4 + threadIdx.x];
            float t0 = targs[base4 + threadIdx.x];
            float s = __expf(-10.0f * p0 * p0);
            float r = __expf(KR * p0);
            float d = p0 - t0;
            for (int j = 0; j < NBINS; j++) {
                atomicAdd(&g_acc[j],         (double)s);
                atomicAdd(&g_acc[NBINS + j], (double)(s * d));
                s *= r;
            }
        }
    }

    // ---- block reduction: warp shuffles, then shared across warps ----
    __shared__ float sh[4][NACC];
    int lane = threadIdx.x & 31;
    int warp = threadIdx.x >> 5;

#pragma unroll
    for (int j = 0; j < NHALF; j++) {
        float alo, ahi, dlo, dhi;
        upk2(A2[j], alo, ahi);
        upk2(D2[j], dlo, dhi);
        float v[4] = {alo, ahi, dlo, dhi};
        // bin indices: A: j, j+10 ; D: 20+j, 30+j
        int idx[4] = {j, j + NHALF, NBINS + j, NBINS + NHALF + j};
#pragma unroll
        for (int q = 0; q < 4; q++) {
            float s = v[q];
#pragma unroll
            for (int off = 16; off; off >>= 1)
                s += __shfl_down_sync(0xffffffffu, s, off);
            if (lane == 0) sh[warp][idx[q]] = s;
        }
    }
    __syncthreads();

    if (threadIdx.x < NACC) {
        double v = (double)sh[0][threadIdx.x] + (double)sh[1][threadIdx.x] +
                   (double)sh[2][threadIdx.x] + (double)sh[3][threadIdx.x];
        atomicAdd(&g_acc[threadIdx.x], v);
    }
    __syncthreads();

    // ---- last block finalizes, writes out, resets state ----
    __shared__ unsigned int s_is_last;
    if (threadIdx.x == 0) {
        __threadfence();
        unsigned int old = atomicAdd(&g_count, 1u);
        s_is_last = (old == gridDim.x - 1) ? 1u : 0u;
    }
    __syncthreads();

    if (s_is_last && threadIdx.x == 0) {
        __threadfence();
        double loss = 0.0;
        for (int j = 0; j < NBINS; j++) {
            double c = (double)j / (double)(NBINS - 1);
            double kj = exp(-c * c / 0.1);         // restores cancelled k_j
            double ws = kj * atomicAdd(&g_acc[j], 0.0);
            double nm = kj * atomicAdd(&g_acc[NBINS + j], 0.0);
            if (ws != 0.0) loss += fabs(nm) / (ws + 1e-8);
        }
        float res = (float)(loss / NBINS);
        for (int i = 0; i < out_size; i++) out[i] = res;
        for (int k = 0; k < NACC; k++) g_acc[k] = 0.0;
        g_count = 0u;
        __threadfence();
    }
}

extern "C" void kernel_launch(void* const* d_in, const int* in_sizes, int n_in,
                              void* d_out, int out_size) {
    const float* preds = (const float*)d_in[0];
    const float* targs = (const float*)d_in[1];
    int n = in_sizes[0];
    // 148 SMs x 6 CTAs/SM = one full wave at occupancy 6
    ace_fused_kernel<<<888, 128>>>(preds, targs, n, (float*)d_out, out_size);
}